// round 16
// baseline (speedup 1.0000x reference)
#include <cuda_runtime.h>
#include <cuda_fp16.h>
#include <math.h>
#include <stdint.h>

#define N_CAP 50048
#define E_CAP 500224
#define KPAD 416
#define NCOL 112

// ---------------- scratch ----------------------------------------------------
__device__ float g_xl[N_CAP * 64];
__device__ float g_xr[N_CAP * 64];
__device__ float g_s1[N_CAP * 4];
__device__ float g_num1[N_CAP * 64];
__device__ float g_s2[N_CAP * 2];
__device__ float g_num2[N_CAP * 32];
__device__ float g_s3[N_CAP];
__device__ float g_num3[N_CAP * 16];
__device__ float g_ea23[E_CAP * 48];
__device__ float g_x3[N_CAP * 16];
__device__ __half g_Bh[NCOL * KPAD];   // [112][416] fp16 weights

// ---------------- helpers ----------------------------------------------------
__device__ __forceinline__ float leakyr(float v) { return v > 0.f ? v : 0.2f * v; }
__device__ __forceinline__ float eluf(float v)   { return v > 0.f ? v : (expf(v) - 1.f); }

__device__ __forceinline__ void red4(float* p, float a, float b, float c, float d) {
    asm volatile("red.global.add.v4.f32 [%0], {%1, %2, %3, %4};"
                 :: "l"(p), "f"(a), "f"(b), "f"(c), "f"(d) : "memory");
}
__device__ __forceinline__ void red2(float* p, float a, float b) {
    asm volatile("red.global.add.v2.f32 [%0], {%1, %2};"
                 :: "l"(p), "f"(a), "f"(b) : "memory");
}
__device__ __forceinline__ void red1(float* p, float a) {
    asm volatile("red.global.add.f32 [%0], %1;" :: "l"(p), "f"(a) : "memory");
}
__device__ __forceinline__ uint32_t smem_u32(const void* p) {
    uint32_t a;
    asm("{ .reg .u64 t; cvta.to.shared.u64 t, %1; cvt.u32.u64 %0, t; }" : "=r"(a) : "l"(p));
    return a;
}
__device__ __forceinline__ void mma_f16(float* d, uint32_t a0, uint32_t a1,
                                        uint32_t a2, uint32_t a3,
                                        uint32_t b0, uint32_t b1) {
    asm volatile(
        "mma.sync.aligned.m16n8k16.row.col.f32.f16.f16.f32 "
        "{%0,%1,%2,%3}, {%4,%5,%6,%7}, {%8,%9}, {%0,%1,%2,%3};"
        : "+f"(d[0]), "+f"(d[1]), "+f"(d[2]), "+f"(d[3])
        : "r"(a0), "r"(a1), "r"(a2), "r"(a3), "r"(b0), "r"(b1));
}
__device__ __forceinline__ void cp16(uint32_t dst_smem, const void* src) {
    asm volatile("cp.async.cg.shared.global [%0], [%1], 16;"
                 :: "r"(dst_smem), "l"(src) : "memory");
}
#define CP_COMMIT()  asm volatile("cp.async.commit_group;" ::: "memory")
#define CP_WAIT(n)   asm volatile("cp.async.wait_group %0;" :: "n"(n) : "memory")

__device__ __forceinline__ uint32_t cvtH16(float x0, float x1) {
    uint32_t h;
    asm("cvt.rn.f16x2.f32 %0, %2, %1;" : "=r"(h) : "f"(x0), "f"(x1));
    return h;
}

// ---------------- weight prep ---------------------------------------------------
__global__ void k_prep_w(const float* __restrict__ We1, const float* __restrict__ We2,
                         const float* __restrict__ We3) {
    int idx = blockIdx.x * blockDim.x + threadIdx.x;
    if (idx >= NCOL * KPAD) return;
    int j = idx / KPAD, k = idx - j * KPAD;
    float w = 0.f;
    if (k < 385) {
        if (j < 64)      w = We1[k * 64 + j];
        else if (j < 96) w = We2[k * 32 + (j - 64)];
        else             w = We3[k * 16 + (j - 96)];
    }
    g_Bh[idx] = __float2half_rn(w);
}

// ---------------- layer 1 node projection + accumulator init -----------------
__global__ void k_node1(const int* __restrict__ node_ids,
                        const float* __restrict__ emb,
                        const float* __restrict__ Wl, const float* __restrict__ bl,
                        const float* __restrict__ Wr, const float* __restrict__ br,
                        int n) {
    int node = blockIdx.x;
    if (node >= n) return;
    int c = threadIdx.x;  // 0..63
    __shared__ float sx[32];
    if (c < 32) sx[c] = emb[node_ids[node] * 32 + c];
    __syncthreads();
    float al = bl[c], ar = br[c];
#pragma unroll
    for (int k = 0; k < 32; k++) {
        float xv = sx[k];
        al += xv * Wl[k * 64 + c];
        ar += xv * Wr[k * 64 + c];
    }
    g_xl[node * 64 + c] = al;
    g_xr[node * 64 + c] = ar;
    g_num1[node * 64 + c] = 0.f;
    if (c < 4) g_s1[node * 4 + c] = 0.f;
}

__global__ void k_noop() {}

// ---------------- pure fp16 mma.sync edge projection (256 thr, 1 tile/warp) --
#define SA_STRIDE 36
#define SB_STRIDE 40
#define SM_AH 0
#define SM_BH (128 * SA_STRIDE * 2)                    // 9216
#define SM_EP_TOTAL (SM_BH + 2 * 112 * SB_STRIDE * 2)  // 27136

__global__ void __launch_bounds__(256, 2) k_edge_mma(
        const float* __restrict__ eattr,
        const int* __restrict__ src, const int* __restrict__ dst,
        const float* __restrict__ att1, int e) {
    extern __shared__ char smem[];
    __half* sAh = reinterpret_cast<__half*>(smem + SM_AH);
    const uint32_t sBh_u = smem_u32(smem + SM_BH);

    const int tid  = threadIdx.x;
    const int w    = tid >> 5;
    const int lane = tid & 31;
    const int g    = lane >> 2;
    const int c    = lane & 3;
    const int eb   = blockIdx.x * 128;
    const int nE   = min(128, e - eb);
    const bool full = (nE == 128);

    float D[14][4];
#pragma unroll
    for (int nt = 0; nt < 14; nt++)
#pragma unroll
        for (int q = 0; q < 4; q++) D[nt][q] = 0.f;

    float aR[16];   // 8 float pairs per thread per chunk

#define LOAD_A_F(kc_)                                                        \
    {                                                                        \
        int k0 = (kc_) * 32;                                                 \
        _Pragma("unroll")                                                    \
        for (int it = 0; it < 8; it++) {                                     \
            int p = it * 256 + tid;                                          \
            int row = p >> 4, cp = p & 15;                                   \
            const float* rp = eattr + (size_t)(eb + row) * 385 + k0 + cp * 2; \
            aR[2 * it] = rp[0]; aR[2 * it + 1] = rp[1];                      \
        }                                                                    \
    }
#define LOAD_A_P(kc_)                                                        \
    {                                                                        \
        int k0 = (kc_) * 32;                                                 \
        _Pragma("unroll")                                                    \
        for (int it = 0; it < 8; it++) {                                     \
            int p = it * 256 + tid;                                          \
            int row = p >> 4, cp = p & 15;                                   \
            float v0 = 0.f, v1 = 0.f;                                        \
            if (row < nE) {                                                  \
                const float* rp = eattr + (size_t)(eb + row) * 385 + k0 + cp * 2; \
                v0 = rp[0]; v1 = rp[1];                                      \
            }                                                                \
            aR[2 * it] = v0; aR[2 * it + 1] = v1;                            \
        }                                                                    \
    }
#define LOAD_A_T()                                                           \
    {                                                                        \
        _Pragma("unroll")                                                    \
        for (int it = 0; it < 8; it++) {                                     \
            int p = it * 256 + tid;                                          \
            int row = p >> 4, cp = p & 15;                                   \
            float v0 = 0.f;                                                  \
            if (cp == 0 && row < nE)                                         \
                v0 = eattr[(size_t)(eb + row) * 385 + 384];                  \
            aR[2 * it] = v0; aR[2 * it + 1] = 0.f;                           \
        }                                                                    \
    }
#define LOAD_A(kc_)                                                          \
    do {                                                                     \
        if ((kc_) >= 12)      LOAD_A_T()                                     \
        else if (full)        LOAD_A_F(kc_)                                  \
        else                  LOAD_A_P(kc_)                                  \
    } while (0)

#define STORE_A()                                                            \
    {                                                                        \
        _Pragma("unroll")                                                    \
        for (int it = 0; it < 8; it++) {                                     \
            int p = it * 256 + tid;                                          \
            int row = p >> 4, cp = p & 15;                                   \
            *reinterpret_cast<uint32_t*>(sAh + row * SA_STRIDE + cp * 2) =   \
                cvtH16(aR[2 * it], aR[2 * it + 1]);                          \
        }                                                                    \
    }

#define CA_B(kc_, buf_)                                                      \
    {                                                                        \
        const char* bh = reinterpret_cast<const char*>(g_Bh);                \
        int koff = (kc_) * 64;                                               \
        uint32_t dsth = sBh_u + (buf_) * 112 * SB_STRIDE * 2;                \
        for (int i = tid; i < 448; i += 256) {                               \
            int row = i >> 2, q = i & 3;                                     \
            cp16(dsth + row * (SB_STRIDE * 2) + q * 16,                      \
                 bh + (size_t)row * (KPAD * 2) + koff + q * 16);             \
        }                                                                    \
    }

    LOAD_A(0);
    CA_B(0, 0);
    CP_COMMIT();

    for (int kc = 0; kc < 13; kc++) {
        __syncthreads();
        STORE_A();
        if (kc < 12) {
            LOAD_A(kc + 1);
            CA_B(kc + 1, (kc + 1) & 1);
            CP_COMMIT();
            CP_WAIT(1);
        } else {
            CP_WAIT(0);
        }
        __syncthreads();

        const __half* bhp = reinterpret_cast<const __half*>(smem + SM_BH)
                            + (kc & 1) * 112 * SB_STRIDE;
#pragma unroll
        for (int k16 = 0; k16 < 2; k16++) {
            int kb = k16 * 16;
            uint32_t ah[4];
            {
                int rA = (w * 16 + g) * SA_STRIDE, rB = rA + 8 * SA_STRIDE;
                int c0 = kb + 2 * c, c1 = kb + 2 * c + 8;
                ah[0] = *reinterpret_cast<const uint32_t*>(sAh + rA + c0);
                ah[1] = *reinterpret_cast<const uint32_t*>(sAh + rB + c0);
                ah[2] = *reinterpret_cast<const uint32_t*>(sAh + rA + c1);
                ah[3] = *reinterpret_cast<const uint32_t*>(sAh + rB + c1);
            }
#pragma unroll
            for (int nt = 0; nt < 14; nt++) {
                int n = nt * 8 + g;
                int c0 = kb + 2 * c, c1 = kb + 2 * c + 8;
                uint32_t bh0 = *reinterpret_cast<const uint32_t*>(bhp + n * SB_STRIDE + c0);
                uint32_t bh1 = *reinterpret_cast<const uint32_t*>(bhp + n * SB_STRIDE + c1);
                mma_f16(D[nt], ah[0], ah[1], ah[2], ah[3], bh0, bh1);
            }
        }
    }

    // -------- epilogue: logits1 -> exp -> fused num1/s1 reduction + ea23 -----
    {
        int rA = w * 16 + g, rB = rA + 8;
        int eeA = eb + rA, eeB = eb + rB;
        bool vA = rA < nE, vB = rB < nE;
        int sA_ = vA ? src[eeA] : 0, dA_ = vA ? dst[eeA] : 0;
        int sB_ = vB ? src[eeB] : 0, dB_ = vB ? dst[eeB] : 0;

        float exA[4], exB[4];
#pragma unroll
        for (int h = 0; h < 4; h++) {
            float pA = 0.f, pB = 0.f;
#pragma unroll
            for (int q = 0; q < 2; q++) {
                int nt = 2 * h + q;
                int col = nt * 8 + c * 2;
                float at0 = att1[col], at1 = att1[col + 1];
                float2 xjA = *reinterpret_cast<const float2*>(g_xl + (size_t)sA_ * 64 + col);
                float2 xiA = *reinterpret_cast<const float2*>(g_xr + (size_t)dA_ * 64 + col);
                pA += leakyr(D[nt][0] + xjA.x + xiA.x) * at0
                    + leakyr(D[nt][1] + xjA.y + xiA.y) * at1;
                float2 xjB = *reinterpret_cast<const float2*>(g_xl + (size_t)sB_ * 64 + col);
                float2 xiB = *reinterpret_cast<const float2*>(g_xr + (size_t)dB_ * 64 + col);
                pB += leakyr(D[nt][2] + xjB.x + xiB.x) * at0
                    + leakyr(D[nt][3] + xjB.y + xiB.y) * at1;
            }
            pA += __shfl_xor_sync(0xFFFFFFFFu, pA, 1);
            pA += __shfl_xor_sync(0xFFFFFFFFu, pA, 2);
            pB += __shfl_xor_sync(0xFFFFFFFFu, pB, 1);
            pB += __shfl_xor_sync(0xFFFFFFFFu, pB, 2);
            exA[h] = expf(pA);
            exB[h] = expf(pB);
            if (c == 0) {
                if (vA) red1(&g_s1[(size_t)dA_ * 4 + h], exA[h]);
                if (vB) red1(&g_s1[(size_t)dB_ * 4 + h], exB[h]);
            }
        }
#pragma unroll
        for (int nt = 0; nt < 8; nt++) {
            int col = nt * 8 + c * 2;
            int h = nt >> 1;
            if (vA) {
                float2 xj = *reinterpret_cast<const float2*>(g_xl + (size_t)sA_ * 64 + col);
                red2(g_num1 + (size_t)dA_ * 64 + col, exA[h] * xj.x, exA[h] * xj.y);
            }
            if (vB) {
                float2 xj = *reinterpret_cast<const float2*>(g_xl + (size_t)sB_ * 64 + col);
                red2(g_num1 + (size_t)dB_ * 64 + col, exB[h] * xj.x, exB[h] * xj.y);
            }
        }
#pragma unroll
        for (int nt = 8; nt < 14; nt++) {
            int off = (nt < 12) ? (nt - 8) * 8 + c * 2
                                : 32 + (nt - 12) * 8 + c * 2;
            if (vA) *reinterpret_cast<float2*>(g_ea23 + (size_t)eeA * 48 + off) =
                        make_float2(D[nt][0], D[nt][1]);
            if (vB) *reinterpret_cast<float2*>(g_ea23 + (size_t)eeB * 48 + off) =
                        make_float2(D[nt][2], D[nt][3]);
        }
    }
}

// ---------------- finish layer1 + project layer2 (16 nodes/block) ------------
__global__ void __launch_bounds__(256) k_node_fin1(
        const float* __restrict__ bias1,
        const float* __restrict__ Wl2, const float* __restrict__ bl2,
        const float* __restrict__ Wr2, const float* __restrict__ br2, int n) {
    __shared__ float sx[16][65];
    int tid = threadIdx.x;
    int nb = blockIdx.x * 16;
#pragma unroll
    for (int i = 0; i < 4; i++) {
        int o = i * 256 + tid;
        int ln = o >> 6, cc = o & 63;
        int node = nb + ln;
        float v = 0.f;
        if (node < n)
            v = g_num1[(size_t)node * 64 + cc] / (g_s1[(size_t)node * 4 + (cc >> 4)] + 1e-16f) + bias1[cc];
        sx[ln][cc] = eluf(v);
    }
    __syncthreads();
    int c = tid & 63, ng = tid >> 6;
    const float* W  = (c < 32) ? Wl2 : Wr2;
    const float* bb = (c < 32) ? bl2 : br2;
    int c2 = c & 31;
    float a[4];
#pragma unroll
    for (int r = 0; r < 4; r++) a[r] = bb[c2];
    for (int k = 0; k < 64; k++) {
        float wv = W[k * 32 + c2];
#pragma unroll
        for (int r = 0; r < 4; r++) a[r] += sx[ng * 4 + r][k] * wv;
    }
#pragma unroll
    for (int r = 0; r < 4; r++) {
        int node = nb + ng * 4 + r;
        if (node < n) {
            if (c < 32) { g_xl[(size_t)node * 32 + c2] = a[r]; g_num2[(size_t)node * 32 + c2] = 0.f; }
            else          g_xr[(size_t)node * 32 + c2] = a[r];
        }
    }
    if (tid < 32) {
        int node = nb + (tid >> 1);
        if (node < n) g_s2[(size_t)node * 2 + (tid & 1)] = 0.f;
    }
}

// ---------------- layer-2 logits + fused softmax (head-correct vector RED) ----
__global__ void k_l2(const int* __restrict__ src, const int* __restrict__ dst,
                     const float* __restrict__ att2, int e) {
    int ee = blockIdx.x * 8 + (threadIdx.x >> 5);
    if (ee >= e) return;
    int c = threadIdx.x & 31;
    int s = src[ee], d = dst[ee];
    float xj = g_xl[(size_t)s * 32 + c];
    float ev = leakyr(xj + g_xr[(size_t)d * 32 + c] + g_ea23[(size_t)ee * 48 + c]);
    float p = ev * att2[c];
    p += __shfl_xor_sync(0xFFFFFFFFu, p, 8);
    p += __shfl_xor_sync(0xFFFFFFFFu, p, 4);
    p += __shfl_xor_sync(0xFFFFFFFFu, p, 2);
    p += __shfl_xor_sync(0xFFFFFFFFu, p, 1);
    float ex = expf(p);
    if ((c & 15) == 0) red1(&g_s2[(size_t)d * 2 + (c >> 4)], ex);
    if ((c & 15) < 4) {
        int col = (c & 16) + (c & 3) * 4;
        float4 x4 = *reinterpret_cast<const float4*>(g_xl + (size_t)s * 32 + col);
        red4(g_num2 + (size_t)d * 32 + col, ex * x4.x, ex * x4.y, ex * x4.z, ex * x4.w);
    }
}

// ---------------- finish layer2 + project layer3 (16 nodes/block) ------------
__global__ void __launch_bounds__(256) k_node_fin2(
        const float* __restrict__ bias2,
        const float* __restrict__ Wl3, const float* __restrict__ bl3,
        const float* __restrict__ Wr3, const float* __restrict__ br3, int n) {
    __shared__ float sx[16][33];
    int tid = threadIdx.x;
    int nb = blockIdx.x * 16;
#pragma unroll
    for (int i = 0; i < 2; i++) {
        int o = i * 256 + tid;
        int ln = o >> 5, cc = o & 31;
        int node = nb + ln;
        float v = 0.f;
        if (node < n)
            v = g_num2[(size_t)node * 32 + cc] / (g_s2[(size_t)node * 2 + (cc >> 4)] + 1e-16f) + bias2[cc];
        sx[ln][cc] = eluf(v);
    }
    __syncthreads();
    int c = tid & 31, ng = tid >> 5;
    const float* W  = (c < 16) ? Wl3 : Wr3;
    const float* bb = (c < 16) ? bl3 : br3;
    int c2 = c & 15;
    float a[2];
    a[0] = bb[c2]; a[1] = bb[c2];
    for (int k = 0; k < 32; k++) {
        float wv = W[k * 16 + c2];
        a[0] += sx[ng * 2 + 0][k] * wv;
        a[1] += sx[ng * 2 + 1][k] * wv;
    }
#pragma unroll
    for (int r = 0; r < 2; r++) {
        int node = nb + ng * 2 + r;
        if (node < n) {
            if (c < 16) { g_xl[(size_t)node * 16 + c2] = a[r]; g_num3[(size_t)node * 16 + c2] = 0.f; }
            else          g_xr[(size_t)node * 16 + c2] = a[r];
        }
    }
    if (tid < 16) {
        int node = nb + tid;
        if (node < n) g_s3[node] = 0.f;
    }
}

// ---------------- layer-3 logits + fused softmax (vector RED, 1 head) ---------
__global__ void k_l3(const int* __restrict__ src, const int* __restrict__ dst,
                     const float* __restrict__ att3, int e) {
    int ee = blockIdx.x * 8 + (threadIdx.x >> 4);
    int c = threadIdx.x & 15;
    bool ok = ee < e;
    int s = ok ? src[ee] : 0, d = ok ? dst[ee] : 0;
    float xj = ok ? g_xl[(size_t)s * 16 + c] : 0.f;
    float ev = ok ? leakyr(xj + g_xr[(size_t)d * 16 + c] + g_ea23[(size_t)ee * 48 + 32 + c]) : 0.f;
    float p = ev * att3[c];
    p += __shfl_xor_sync(0xFFFFFFFFu, p, 8);
    p += __shfl_xor_sync(0xFFFFFFFFu, p, 4);
    p += __shfl_xor_sync(0xFFFFFFFFu, p, 2);
    p += __shfl_xor_sync(0xFFFFFFFFu, p, 1);
    if (ok) {
        float ex = expf(p);
        if (c == 0) red1(&g_s3[d], ex);
        if (c < 4) {
            float4 x4 = *reinterpret_cast<const float4*>(g_xl + (size_t)s * 16 + c * 4);
            red4(g_num3 + (size_t)d * 16 + c * 4, ex * x4.x, ex * x4.y, ex * x4.z, ex * x4.w);
        }
    }
}

// ---------------- finish layer3 ------------------------------------------------
__global__ void k_node_fin3(const float* __restrict__ bias3, int n) {
    int i = blockIdx.x * blockDim.x + threadIdx.x;
    if (i >= n * 16) return;
    g_x3[i] = g_num3[i] / (g_s3[i >> 4] + 1e-16f) + bias3[i & 15];
}

// ---------------- P/Q precompute -----------------------------------------------
__global__ void __launch_bounds__(256) k_pq(const float* __restrict__ W1, int n) {
    __shared__ float w1s[32 * 64];
    __shared__ float x3s[16][17];
    int tid = threadIdx.x;
    int nb = blockIdx.x * 16;
    for (int i = tid; i < 512; i += 256)
        reinterpret_cast<float4*>(w1s)[i] = reinterpret_cast<const float4*>(W1)[i];
    {
        int node = tid >> 4, k = tid & 15;
        x3s[node][k] = (nb + node < n) ? g_x3[(size_t)(nb + node) * 16 + k] : 0.f;
    }
    __syncthreads();
#pragma unroll
    for (int i = 0; i < 8; i++) {
        int o = i * 256 + tid;
        int node = o >> 7, col = o & 127;
        int hh = col >> 6, j = col & 63;
        float acc = 0.f;
#pragma unroll
        for (int k = 0; k < 16; k++) acc += x3s[node][k] * w1s[(hh * 16 + k) * 64 + j];
        if (nb + node < n) {
            if (hh == 0) g_xl[(size_t)(nb + node) * 64 + j] = acc;
            else         g_xr[(size_t)(nb + node) * 64 + j] = acc;
        }
    }
}

// ---------------- edge MLP: 32 edges/block using P/Q ---------------------------
__global__ void __launch_bounds__(256) k_mlp(
        const int* __restrict__ src, const int* __restrict__ dst,
        const float* __restrict__ b1, const float* __restrict__ W2,
        const float* __restrict__ b2, const float* __restrict__ W3,
        const float* __restrict__ b3, float* __restrict__ out, int e) {
    __shared__ float w2s[64 * 32];
    __shared__ float h1s[32][68];
    __shared__ float h2s[32][33];
    __shared__ int   se[32], de[32];
    __shared__ float w3s[32];
    int tid = threadIdx.x;
    int eb = blockIdx.x * 32;

    for (int i = tid; i < 512; i += 256)
        reinterpret_cast<float4*>(w2s)[i] = reinterpret_cast<const float4*>(W2)[i];
    if (tid < 32) {
        int ee = eb + tid;
        se[tid] = (ee < e) ? src[ee] : 0;
        de[tid] = (ee < e) ? dst[ee] : 0;
        w3s[tid] = W3[tid];
    }
    __syncthreads();

#pragma unroll
    for (int i = 0; i < 8; i++) {
        int o = i * 256 + tid;
        int le = o >> 6, j = o & 63;
        float v = g_xl[(size_t)se[le] * 64 + j] + g_xr[(size_t)de[le] * 64 + j] + b1[j];
        h1s[le][j] = fmaxf(v, 0.f);
    }
    __syncthreads();

    if (tid < 128) {
        int j = tid & 31, eg = tid >> 5;
        float acc[8];
#pragma unroll
        for (int r = 0; r < 8; r++) acc[r] = b2[j];
#pragma unroll
        for (int k4 = 0; k4 < 16; k4++) {
            int k = k4 * 4;
            float w0 = w2s[(k + 0) * 32 + j];
            float w1 = w2s[(k + 1) * 32 + j];
            float w2v = w2s[(k + 2) * 32 + j];
            float w3v = w2s[(k + 3) * 32 + j];
#pragma unroll
            for (int r = 0; r < 8; r++) {
                float4 hv = *reinterpret_cast<const float4*>(&h1s[eg * 8 + r][k]);
                acc[r] += hv.x * w0 + hv.y * w1 + hv.z * w2v + hv.w * w3v;
            }
        }
#pragma unroll
        for (int r = 0; r < 8; r++) h2s[eg * 8 + r][j] = fmaxf(acc[r], 0.f);
    }
    __syncthreads();

    if (tid < 32) {
        float p = 0.f;
#pragma unroll
        for (int k = 0; k < 32; k++) p += h2s[tid][k] * w3s[k];
        int ee = eb + tid;
        if (ee < e) out[ee] = p + b3[0];
    }
}

// ---------------- launch --------------------------------------------------------
extern "C" void kernel_launch(void* const* d_in, const int* in_sizes, int n_in,
                              void* d_out, int out_size) {
    const int*   node_ids = (const int*)  d_in[0];
    const int*   eidx     = (const int*)  d_in[1];
    const float* eattr    = (const float*)d_in[2];
    const float* emb      = (const float*)d_in[3];
    const float* l1_Wl   = (const float*)d_in[4];
    const float* l1_bl   = (const float*)d_in[5];
    const float* l1_Wr   = (const float*)d_in[6];
    const float* l1_br   = (const float*)d_in[7];
    const float* l1_We   = (const float*)d_in[8];
    const float* l1_att  = (const float*)d_in[9];
    const float* l1_bias = (const float*)d_in[10];
    const float* l2_Wl   = (const float*)d_in[11];
    const float* l2_bl   = (const float*)d_in[12];
    const float* l2_Wr   = (const float*)d_in[13];
    const float* l2_br   = (const float*)d_in[14];
    const float* l2_We   = (const float*)d_in[15];
    const float* l2_att  = (const float*)d_in[16];
    const float* l2_bias = (const float*)d_in[17];
    const float* l3_Wl   = (const float*)d_in[18];
    const float* l3_bl   = (const float*)d_in[19];
    const float* l3_Wr   = (const float*)d_in[20];
    const float* l3_br   = (const float*)d_in[21];
    const float* l3_We   = (const float*)d_in[22];
    const float* l3_att  = (const float*)d_in[23];
    const float* l3_bias = (const float*)d_in[24];
    const float* mlp_W1  = (const float*)d_in[25];
    const float* mlp_b1  = (const float*)d_in[26];
    const float* mlp_W2  = (const float*)d_in[27];
    const float* mlp_b2  = (const float*)d_in[28];
    const float* mlp_W3  = (const float*)d_in[29];
    const float* mlp_b3  = (const float*)d_in[30];

    int n = in_sizes[0];
    int e = in_sizes[1] / 2;
    const int* src = eidx;
    const int* dst = eidx + e;
    float* out = (float*)d_out;

    static bool attr_set = false;
    if (!attr_set) {
        cudaFuncSetAttribute(k_edge_mma, cudaFuncAttributeMaxDynamicSharedMemorySize, SM_EP_TOTAL);
        attr_set = true;
    }

    // ---- prep + layer 1 (edge GEMM stays launch #4 for ncu) ----
    k_prep_w<<<(NCOL * KPAD + 255) / 256, 256>>>(l1_We, l2_We, l3_We);
    k_node1<<<n, 64>>>(node_ids, emb, l1_Wl, l1_bl, l1_Wr, l1_br, n);
    k_noop<<<1, 32>>>();
    k_edge_mma<<<(e + 127) / 128, 256, SM_EP_TOTAL>>>(eattr, src, dst, l1_att, e);
    k_node_fin1<<<(n + 15) / 16, 256>>>(l1_bias, l2_Wl, l2_bl, l2_Wr, l2_br, n);

    // ---- layer 2 ----
    k_l2<<<(e + 7) / 8, 256>>>(src, dst, l2_att, e);
    k_node_fin2<<<(n + 15) / 16, 256>>>(l2_bias, l3_Wl, l3_bl, l3_Wr, l3_br, n);

    // ---- layer 3 ----
    k_l3<<<(e + 7) / 8, 128>>>(src, dst, l3_att, e);
    k_node_fin3<<<(n * 16 + 255) / 256, 256>>>(l3_bias, n);

    // ---- edge MLP via P/Q ----
    k_pq<<<(n + 15) / 16, 256>>>(mlp_W1, n);
    k_mlp<<<(e + 31) / 32, 256>>>(src, dst, mlp_b1, mlp_W2, mlp_b2,
                                  mlp_W3, mlp_b3, out, e);
}

// round 17
// speedup vs baseline: 1.5284x; 1.5284x over previous
#include <cuda_runtime.h>
#include <cuda_fp16.h>
#include <math.h>
#include <stdint.h>

#define N_CAP 50048
#define E_CAP 500224
#define KPAD 416
#define NCOL 112

// ---------------- scratch ----------------------------------------------------
__device__ float g_xl[N_CAP * 64];
__device__ float g_xr[N_CAP * 64];
__device__ float g_s1[N_CAP * 4];
__device__ float g_num1[N_CAP * 64];
__device__ float g_s2[N_CAP * 2];
__device__ float g_num2[N_CAP * 32];
__device__ float g_s3[N_CAP];
__device__ float g_num3[N_CAP * 16];
__device__ float g_ea23[E_CAP * 48];
__device__ float g_x3[N_CAP * 16];
__device__ __half g_Bh[NCOL * KPAD];   // [112][416] fp16 weights

// ---------------- helpers ----------------------------------------------------
__device__ __forceinline__ float leakyr(float v) { return v > 0.f ? v : 0.2f * v; }
__device__ __forceinline__ float eluf(float v)   { return v > 0.f ? v : (expf(v) - 1.f); }

__device__ __forceinline__ void red4(float* p, float a, float b, float c, float d) {
    asm volatile("red.global.add.v4.f32 [%0], {%1, %2, %3, %4};"
                 :: "l"(p), "f"(a), "f"(b), "f"(c), "f"(d) : "memory");
}
__device__ __forceinline__ void red2(float* p, float a, float b) {
    asm volatile("red.global.add.v2.f32 [%0], {%1, %2};"
                 :: "l"(p), "f"(a), "f"(b) : "memory");
}
__device__ __forceinline__ void red1(float* p, float a) {
    asm volatile("red.global.add.f32 [%0], %1;" :: "l"(p), "f"(a) : "memory");
}
__device__ __forceinline__ uint32_t smem_u32(const void* p) {
    uint32_t a;
    asm("{ .reg .u64 t; cvta.to.shared.u64 t, %1; cvt.u32.u64 %0, t; }" : "=r"(a) : "l"(p));
    return a;
}
__device__ __forceinline__ void mma_f16(float* d, uint32_t a0, uint32_t a1,
                                        uint32_t a2, uint32_t a3,
                                        uint32_t b0, uint32_t b1) {
    asm volatile(
        "mma.sync.aligned.m16n8k16.row.col.f32.f16.f16.f32 "
        "{%0,%1,%2,%3}, {%4,%5,%6,%7}, {%8,%9}, {%0,%1,%2,%3};"
        : "+f"(d[0]), "+f"(d[1]), "+f"(d[2]), "+f"(d[3])
        : "r"(a0), "r"(a1), "r"(a2), "r"(a3), "r"(b0), "r"(b1));
}
__device__ __forceinline__ void cp16(uint32_t dst_smem, const void* src) {
    asm volatile("cp.async.cg.shared.global [%0], [%1], 16;"
                 :: "r"(dst_smem), "l"(src) : "memory");
}
#define CP_COMMIT()  asm volatile("cp.async.commit_group;" ::: "memory")
#define CP_WAIT(n)   asm volatile("cp.async.wait_group %0;" :: "n"(n) : "memory")

__device__ __forceinline__ uint32_t cvtH16(float x0, float x1) {
    uint32_t h;
    asm("cvt.rn.f16x2.f32 %0, %2, %1;" : "=r"(h) : "f"(x0), "f"(x1));
    return h;
}

// ---------------- weight prep ---------------------------------------------------
__global__ void k_prep_w(const float* __restrict__ We1, const float* __restrict__ We2,
                         const float* __restrict__ We3) {
    int idx = blockIdx.x * blockDim.x + threadIdx.x;
    if (idx >= NCOL * KPAD) return;
    int j = idx / KPAD, k = idx - j * KPAD;
    float w = 0.f;
    if (k < 385) {
        if (j < 64)      w = We1[k * 64 + j];
        else if (j < 96) w = We2[k * 32 + (j - 64)];
        else             w = We3[k * 16 + (j - 96)];
    }
    g_Bh[idx] = __float2half_rn(w);
}

// ---------------- layer 1 node projection (16 nodes/block) + init -------------
__global__ void __launch_bounds__(256) k_node1(
        const int* __restrict__ node_ids, const float* __restrict__ emb,
        const float* __restrict__ Wl, const float* __restrict__ bl,
        const float* __restrict__ Wr, const float* __restrict__ br, int n) {
    __shared__ float sx[16][33];
    int tid = threadIdx.x;
    int nb = blockIdx.x * 16;
    for (int i = tid; i < 512; i += 256) {
        int ln = i >> 5, k = i & 31;
        int node = nb + ln;
        sx[ln][k] = (node < n) ? emb[(size_t)node_ids[node] * 32 + k] : 0.f;
    }
    __syncthreads();
    int c = tid & 63;
    int grp = tid >> 6;              // 0..3
    int side = grp >> 1, ng = grp & 1;   // side: 0=Wl, 1=Wr; ng: node group of 8
    const float* W  = side ? Wr : Wl;
    const float* bb = side ? br : bl;
    float a[8];
#pragma unroll
    for (int r = 0; r < 8; r++) a[r] = bb[c];
    for (int k = 0; k < 32; k++) {
        float wv = W[k * 64 + c];
#pragma unroll
        for (int r = 0; r < 8; r++) a[r] += sx[ng * 8 + r][k] * wv;
    }
#pragma unroll
    for (int r = 0; r < 8; r++) {
        int node = nb + ng * 8 + r;
        if (node < n) {
            if (side == 0) {
                g_xl[(size_t)node * 64 + c] = a[r];
                g_num1[(size_t)node * 64 + c] = 0.f;
            } else {
                g_xr[(size_t)node * 64 + c] = a[r];
            }
        }
    }
    if (tid < 64) {
        int node = nb + (tid >> 2);
        if (node < n) g_s1[(size_t)node * 4 + (tid & 3)] = 0.f;
    }
}

__global__ void k_noop() {}

// ---------------- pure fp16 mma.sync edge projection + fused softmax (R15) ----
#define SA_STRIDE 36
#define SB_STRIDE 40
#define SM_AH 0
#define SM_BH (128 * SA_STRIDE * 2)                    // 9216
#define SM_EP_TOTAL (SM_BH + 2 * 112 * SB_STRIDE * 2)  // 27136

__global__ void __launch_bounds__(128, 2) k_edge_mma(
        const float* __restrict__ eattr,
        const int* __restrict__ src, const int* __restrict__ dst,
        const float* __restrict__ att1, int e) {
    extern __shared__ char smem[];
    __half* sAh = reinterpret_cast<__half*>(smem + SM_AH);
    const uint32_t sBh_u = smem_u32(smem + SM_BH);

    const int tid  = threadIdx.x;
    const int w    = tid >> 5;
    const int lane = tid & 31;
    const int g    = lane >> 2;
    const int c    = lane & 3;
    const int eb   = blockIdx.x * 128;
    const int nE   = min(128, e - eb);
    const bool full = (nE == 128);

    float D[2][14][4];
#pragma unroll
    for (int tt = 0; tt < 2; tt++)
#pragma unroll
        for (int nt = 0; nt < 14; nt++)
#pragma unroll
            for (int q = 0; q < 4; q++) D[tt][nt][q] = 0.f;

    float aR[32];

#define LOAD_A_F(kc_)                                                        \
    {                                                                        \
        int k0 = (kc_) * 32;                                                 \
        _Pragma("unroll")                                                    \
        for (int it = 0; it < 16; it++) {                                    \
            int p = it * 128 + tid;                                          \
            int row = p >> 4, cp = p & 15;                                   \
            const float* rp = eattr + (size_t)(eb + row) * 385 + k0 + cp * 2; \
            aR[2 * it] = rp[0]; aR[2 * it + 1] = rp[1];                      \
        }                                                                    \
    }
#define LOAD_A_P(kc_)                                                        \
    {                                                                        \
        int k0 = (kc_) * 32;                                                 \
        _Pragma("unroll")                                                    \
        for (int it = 0; it < 16; it++) {                                    \
            int p = it * 128 + tid;                                          \
            int row = p >> 4, cp = p & 15;                                   \
            float v0 = 0.f, v1 = 0.f;                                        \
            if (row < nE) {                                                  \
                const float* rp = eattr + (size_t)(eb + row) * 385 + k0 + cp * 2; \
                v0 = rp[0]; v1 = rp[1];                                      \
            }                                                                \
            aR[2 * it] = v0; aR[2 * it + 1] = v1;                            \
        }                                                                    \
    }
#define LOAD_A_T()                                                           \
    {                                                                        \
        _Pragma("unroll")                                                    \
        for (int it = 0; it < 16; it++) {                                    \
            int p = it * 128 + tid;                                          \
            int row = p >> 4, cp = p & 15;                                   \
            float v0 = 0.f;                                                  \
            if (cp == 0 && row < nE)                                         \
                v0 = eattr[(size_t)(eb + row) * 385 + 384];                  \
            aR[2 * it] = v0; aR[2 * it + 1] = 0.f;                           \
        }                                                                    \
    }
#define LOAD_A(kc_)                                                          \
    do {                                                                     \
        if ((kc_) >= 12)      LOAD_A_T()                                     \
        else if (full)        LOAD_A_F(kc_)                                  \
        else                  LOAD_A_P(kc_)                                  \
    } while (0)

#define STORE_A()                                                            \
    {                                                                        \
        _Pragma("unroll")                                                    \
        for (int it = 0; it < 16; it++) {                                    \
            int p = it * 128 + tid;                                          \
            int row = p >> 4, cp = p & 15;                                   \
            *reinterpret_cast<uint32_t*>(sAh + row * SA_STRIDE + cp * 2) =   \
                cvtH16(aR[2 * it], aR[2 * it + 1]);                          \
        }                                                                    \
    }

#define CA_B(kc_, buf_)                                                      \
    {                                                                        \
        const char* bh = reinterpret_cast<const char*>(g_Bh);                \
        int koff = (kc_) * 64;                                               \
        uint32_t dsth = sBh_u + (buf_) * 112 * SB_STRIDE * 2;                \
        for (int i = tid; i < 448; i += 128) {                               \
            int row = i >> 2, q = i & 3;                                     \
            cp16(dsth + row * (SB_STRIDE * 2) + q * 16,                      \
                 bh + (size_t)row * (KPAD * 2) + koff + q * 16);             \
        }                                                                    \
    }

    LOAD_A(0);
    CA_B(0, 0);
    CP_COMMIT();

    for (int kc = 0; kc < 13; kc++) {
        __syncthreads();
        STORE_A();
        if (kc < 12) {
            LOAD_A(kc + 1);
            CA_B(kc + 1, (kc + 1) & 1);
            CP_COMMIT();
            CP_WAIT(1);
        } else {
            CP_WAIT(0);
        }
        __syncthreads();

        const __half* bhp = reinterpret_cast<const __half*>(smem + SM_BH)
                            + (kc & 1) * 112 * SB_STRIDE;
#pragma unroll
        for (int k16 = 0; k16 < 2; k16++) {
            int kb = k16 * 16;
            uint32_t ah[2][4];
#pragma unroll
            for (int tt = 0; tt < 2; tt++) {
                int m0 = w * 32 + tt * 16;
                int rA = (m0 + g) * SA_STRIDE, rB = (m0 + g + 8) * SA_STRIDE;
                int c0 = kb + 2 * c, c1 = kb + 2 * c + 8;
                ah[tt][0] = *reinterpret_cast<const uint32_t*>(sAh + rA + c0);
                ah[tt][1] = *reinterpret_cast<const uint32_t*>(sAh + rB + c0);
                ah[tt][2] = *reinterpret_cast<const uint32_t*>(sAh + rA + c1);
                ah[tt][3] = *reinterpret_cast<const uint32_t*>(sAh + rB + c1);
            }
#pragma unroll
            for (int nt = 0; nt < 14; nt++) {
                int n = nt * 8 + g;
                int c0 = kb + 2 * c, c1 = kb + 2 * c + 8;
                uint32_t bh0 = *reinterpret_cast<const uint32_t*>(bhp + n * SB_STRIDE + c0);
                uint32_t bh1 = *reinterpret_cast<const uint32_t*>(bhp + n * SB_STRIDE + c1);
#pragma unroll
                for (int tt = 0; tt < 2; tt++)
                    mma_f16(D[tt][nt], ah[tt][0], ah[tt][1], ah[tt][2], ah[tt][3], bh0, bh1);
            }
        }
    }

    // -------- epilogue --------
#pragma unroll
    for (int tt = 0; tt < 2; tt++) {
        int m0 = w * 32 + tt * 16;
        int rA = m0 + g, rB = m0 + g + 8;
        int eeA = eb + rA, eeB = eb + rB;
        bool vA = rA < nE, vB = rB < nE;
        int sA_ = vA ? src[eeA] : 0, dA_ = vA ? dst[eeA] : 0;
        int sB_ = vB ? src[eeB] : 0, dB_ = vB ? dst[eeB] : 0;

        float exA[4], exB[4];
#pragma unroll
        for (int h = 0; h < 4; h++) {
            float pA = 0.f, pB = 0.f;
#pragma unroll
            for (int q = 0; q < 2; q++) {
                int nt = 2 * h + q;
                int col = nt * 8 + c * 2;
                float at0 = att1[col], at1 = att1[col + 1];
                float2 xjA = *reinterpret_cast<const float2*>(g_xl + (size_t)sA_ * 64 + col);
                float2 xiA = *reinterpret_cast<const float2*>(g_xr + (size_t)dA_ * 64 + col);
                pA += leakyr(D[tt][nt][0] + xjA.x + xiA.x) * at0
                    + leakyr(D[tt][nt][1] + xjA.y + xiA.y) * at1;
                float2 xjB = *reinterpret_cast<const float2*>(g_xl + (size_t)sB_ * 64 + col);
                float2 xiB = *reinterpret_cast<const float2*>(g_xr + (size_t)dB_ * 64 + col);
                pB += leakyr(D[tt][nt][2] + xjB.x + xiB.x) * at0
                    + leakyr(D[tt][nt][3] + xjB.y + xiB.y) * at1;
            }
            pA += __shfl_xor_sync(0xFFFFFFFFu, pA, 1);
            pA += __shfl_xor_sync(0xFFFFFFFFu, pA, 2);
            pB += __shfl_xor_sync(0xFFFFFFFFu, pB, 1);
            pB += __shfl_xor_sync(0xFFFFFFFFu, pB, 2);
            exA[h] = expf(pA);
            exB[h] = expf(pB);
            if (c == 0) {
                if (vA) red1(&g_s1[(size_t)dA_ * 4 + h], exA[h]);
                if (vB) red1(&g_s1[(size_t)dB_ * 4 + h], exB[h]);
            }
        }
#pragma unroll
        for (int nt = 0; nt < 8; nt++) {
            int col = nt * 8 + c * 2;
            int h = nt >> 1;
            if (vA) {
                float2 xj = *reinterpret_cast<const float2*>(g_xl + (size_t)sA_ * 64 + col);
                red2(g_num1 + (size_t)dA_ * 64 + col, exA[h] * xj.x, exA[h] * xj.y);
            }
            if (vB) {
                float2 xj = *reinterpret_cast<const float2*>(g_xl + (size_t)sB_ * 64 + col);
                red2(g_num1 + (size_t)dB_ * 64 + col, exB[h] * xj.x, exB[h] * xj.y);
            }
        }
#pragma unroll
        for (int nt = 8; nt < 14; nt++) {
            int off = (nt < 12) ? (nt - 8) * 8 + c * 2
                                : 32 + (nt - 12) * 8 + c * 2;
            if (vA) *reinterpret_cast<float2*>(g_ea23 + (size_t)eeA * 48 + off) =
                        make_float2(D[tt][nt][0], D[tt][nt][1]);
            if (vB) *reinterpret_cast<float2*>(g_ea23 + (size_t)eeB * 48 + off) =
                        make_float2(D[tt][nt][2], D[tt][nt][3]);
        }
    }
}

// ---------------- finish layer1 + project layer2 (16 nodes/block) ------------
__global__ void __launch_bounds__(256) k_node_fin1(
        const float* __restrict__ bias1,
        const float* __restrict__ Wl2, const float* __restrict__ bl2,
        const float* __restrict__ Wr2, const float* __restrict__ br2, int n) {
    __shared__ float sx[16][65];
    int tid = threadIdx.x;
    int nb = blockIdx.x * 16;
#pragma unroll
    for (int i = 0; i < 4; i++) {
        int o = i * 256 + tid;
        int ln = o >> 6, cc = o & 63;
        int node = nb + ln;
        float v = 0.f;
        if (node < n)
            v = g_num1[(size_t)node * 64 + cc] / (g_s1[(size_t)node * 4 + (cc >> 4)] + 1e-16f) + bias1[cc];
        sx[ln][cc] = eluf(v);
    }
    __syncthreads();
    int c = tid & 63, ng = tid >> 6;
    const float* W  = (c < 32) ? Wl2 : Wr2;
    const float* bb = (c < 32) ? bl2 : br2;
    int c2 = c & 31;
    float a[4];
#pragma unroll
    for (int r = 0; r < 4; r++) a[r] = bb[c2];
    for (int k = 0; k < 64; k++) {
        float wv = W[k * 32 + c2];
#pragma unroll
        for (int r = 0; r < 4; r++) a[r] += sx[ng * 4 + r][k] * wv;
    }
#pragma unroll
    for (int r = 0; r < 4; r++) {
        int node = nb + ng * 4 + r;
        if (node < n) {
            if (c < 32) { g_xl[(size_t)node * 32 + c2] = a[r]; g_num2[(size_t)node * 32 + c2] = 0.f; }
            else          g_xr[(size_t)node * 32 + c2] = a[r];
        }
    }
    if (tid < 32) {
        int node = nb + (tid >> 1);
        if (node < n) g_s2[(size_t)node * 2 + (tid & 1)] = 0.f;
    }
}

// ---------------- layer-2 logits + fused softmax (head-correct vector RED) ----
__global__ void k_l2(const int* __restrict__ src, const int* __restrict__ dst,
                     const float* __restrict__ att2, int e) {
    int ee = blockIdx.x * 8 + (threadIdx.x >> 5);
    if (ee >= e) return;
    int c = threadIdx.x & 31;
    int s = src[ee], d = dst[ee];
    float xj = g_xl[(size_t)s * 32 + c];
    float ev = leakyr(xj + g_xr[(size_t)d * 32 + c] + g_ea23[(size_t)ee * 48 + c]);
    float p = ev * att2[c];
    p += __shfl_xor_sync(0xFFFFFFFFu, p, 8);
    p += __shfl_xor_sync(0xFFFFFFFFu, p, 4);
    p += __shfl_xor_sync(0xFFFFFFFFu, p, 2);
    p += __shfl_xor_sync(0xFFFFFFFFu, p, 1);
    float ex = expf(p);
    if ((c & 15) == 0) red1(&g_s2[(size_t)d * 2 + (c >> 4)], ex);
    if ((c & 15) < 4) {
        int col = (c & 16) + (c & 3) * 4;
        float4 x4 = *reinterpret_cast<const float4*>(g_xl + (size_t)s * 32 + col);
        red4(g_num2 + (size_t)d * 32 + col, ex * x4.x, ex * x4.y, ex * x4.z, ex * x4.w);
    }
}

// ---------------- finish layer2 + project layer3 (16 nodes/block) ------------
__global__ void __launch_bounds__(256) k_node_fin2(
        const float* __restrict__ bias2,
        const float* __restrict__ Wl3, const float* __restrict__ bl3,
        const float* __restrict__ Wr3, const float* __restrict__ br3, int n) {
    __shared__ float sx[16][33];
    int tid = threadIdx.x;
    int nb = blockIdx.x * 16;
#pragma unroll
    for (int i = 0; i < 2; i++) {
        int o = i * 256 + tid;
        int ln = o >> 5, cc = o & 31;
        int node = nb + ln;
        float v = 0.f;
        if (node < n)
            v = g_num2[(size_t)node * 32 + cc] / (g_s2[(size_t)node * 2 + (cc >> 4)] + 1e-16f) + bias2[cc];
        sx[ln][cc] = eluf(v);
    }
    __syncthreads();
    int c = tid & 31, ng = tid >> 5;
    const float* W  = (c < 16) ? Wl3 : Wr3;
    const float* bb = (c < 16) ? bl3 : br3;
    int c2 = c & 15;
    float a[2];
    a[0] = bb[c2]; a[1] = bb[c2];
    for (int k = 0; k < 32; k++) {
        float wv = W[k * 16 + c2];
        a[0] += sx[ng * 2 + 0][k] * wv;
        a[1] += sx[ng * 2 + 1][k] * wv;
    }
#pragma unroll
    for (int r = 0; r < 2; r++) {
        int node = nb + ng * 2 + r;
        if (node < n) {
            if (c < 16) { g_xl[(size_t)node * 16 + c2] = a[r]; g_num3[(size_t)node * 16 + c2] = 0.f; }
            else          g_xr[(size_t)node * 16 + c2] = a[r];
        }
    }
    if (tid < 16) {
        int node = nb + tid;
        if (node < n) g_s3[node] = 0.f;
    }
}

// ---------------- layer-3 logits + fused softmax (vector RED, 1 head) ---------
__global__ void k_l3(const int* __restrict__ src, const int* __restrict__ dst,
                     const float* __restrict__ att3, int e) {
    int ee = blockIdx.x * 8 + (threadIdx.x >> 4);
    int c = threadIdx.x & 15;
    bool ok = ee < e;
    int s = ok ? src[ee] : 0, d = ok ? dst[ee] : 0;
    float xj = ok ? g_xl[(size_t)s * 16 + c] : 0.f;
    float ev = ok ? leakyr(xj + g_xr[(size_t)d * 16 + c] + g_ea23[(size_t)ee * 48 + 32 + c]) : 0.f;
    float p = ev * att3[c];
    p += __shfl_xor_sync(0xFFFFFFFFu, p, 8);
    p += __shfl_xor_sync(0xFFFFFFFFu, p, 4);
    p += __shfl_xor_sync(0xFFFFFFFFu, p, 2);
    p += __shfl_xor_sync(0xFFFFFFFFu, p, 1);
    if (ok) {
        float ex = expf(p);
        if (c == 0) red1(&g_s3[d], ex);
        if (c < 4) {
            float4 x4 = *reinterpret_cast<const float4*>(g_xl + (size_t)s * 16 + c * 4);
            red4(g_num3 + (size_t)d * 16 + c * 4, ex * x4.x, ex * x4.y, ex * x4.z, ex * x4.w);
        }
    }
}

// ---------------- finish layer3 ------------------------------------------------
__global__ void k_node_fin3(const float* __restrict__ bias3, int n) {
    int i = blockIdx.x * blockDim.x + threadIdx.x;
    if (i >= n * 16) return;
    g_x3[i] = g_num3[i] / (g_s3[i >> 4] + 1e-16f) + bias3[i & 15];
}

// ---------------- P/Q precompute -----------------------------------------------
__global__ void __launch_bounds__(256) k_pq(const float* __restrict__ W1, int n) {
    __shared__ float w1s[32 * 64];
    __shared__ float x3s[16][17];
    int tid = threadIdx.x;
    int nb = blockIdx.x * 16;
    for (int i = tid; i < 512; i += 256)
        reinterpret_cast<float4*>(w1s)[i] = reinterpret_cast<const float4*>(W1)[i];
    {
        int node = tid >> 4, k = tid & 15;
        x3s[node][k] = (nb + node < n) ? g_x3[(size_t)(nb + node) * 16 + k] : 0.f;
    }
    __syncthreads();
#pragma unroll
    for (int i = 0; i < 8; i++) {
        int o = i * 256 + tid;
        int node = o >> 7, col = o & 127;
        int hh = col >> 6, j = col & 63;
        float acc = 0.f;
#pragma unroll
        for (int k = 0; k < 16; k++) acc += x3s[node][k] * w1s[(hh * 16 + k) * 64 + j];
        if (nb + node < n) {
            if (hh == 0) g_xl[(size_t)(nb + node) * 64 + j] = acc;
            else         g_xr[(size_t)(nb + node) * 64 + j] = acc;
        }
    }
}

// ---------------- edge MLP: 64 edges/block using P/Q ---------------------------
__global__ void __launch_bounds__(256) k_mlp(
        const int* __restrict__ src, const int* __restrict__ dst,
        const float* __restrict__ b1, const float* __restrict__ W2,
        const float* __restrict__ b2, const float* __restrict__ W3,
        const float* __restrict__ b3, float* __restrict__ out, int e) {
    __shared__ float w2s[64 * 32];
    __shared__ float h1s[64][68];
    __shared__ float h2s[64][33];
    __shared__ int   se[64], de[64];
    __shared__ float w3s[32];
    int tid = threadIdx.x;
    int eb = blockIdx.x * 64;

    for (int i = tid; i < 512; i += 256)
        reinterpret_cast<float4*>(w2s)[i] = reinterpret_cast<const float4*>(W2)[i];
    if (tid < 64) {
        int ee = eb + tid;
        se[tid] = (ee < e) ? src[ee] : 0;
        de[tid] = (ee < e) ? dst[ee] : 0;
    }
    if (tid < 32) w3s[tid] = W3[tid];
    __syncthreads();

#pragma unroll
    for (int i = 0; i < 16; i++) {
        int o = i * 256 + tid;
        int le = o >> 6, j = o & 63;
        float v = g_xl[(size_t)se[le] * 64 + j] + g_xr[(size_t)de[le] * 64 + j] + b1[j];
        h1s[le][j] = fmaxf(v, 0.f);
    }
    __syncthreads();

    {
        int j = tid & 31, eg = tid >> 5;   // 8 groups of 8 edges
        float acc[8];
#pragma unroll
        for (int r = 0; r < 8; r++) acc[r] = b2[j];
#pragma unroll
        for (int k4 = 0; k4 < 16; k4++) {
            int k = k4 * 4;
            float w0 = w2s[(k + 0) * 32 + j];
            float w1 = w2s[(k + 1) * 32 + j];
            float w2v = w2s[(k + 2) * 32 + j];
            float w3v = w2s[(k + 3) * 32 + j];
#pragma unroll
            for (int r = 0; r < 8; r++) {
                float4 hv = *reinterpret_cast<const float4*>(&h1s[eg * 8 + r][k]);
                acc[r] += hv.x * w0 + hv.y * w1 + hv.z * w2v + hv.w * w3v;
            }
        }
#pragma unroll
        for (int r = 0; r < 8; r++) h2s[eg * 8 + r][j] = fmaxf(acc[r], 0.f);
    }
    __syncthreads();

    if (tid < 64) {
        float p = 0.f;
#pragma unroll
        for (int k = 0; k < 32; k++) p += h2s[tid][k] * w3s[k];
        int ee = eb + tid;
        if (ee < e) out[ee] = p + b3[0];
    }
}

// ---------------- launch --------------------------------------------------------
extern "C" void kernel_launch(void* const* d_in, const int* in_sizes, int n_in,
                              void* d_out, int out_size) {
    const int*   node_ids = (const int*)  d_in[0];
    const int*   eidx     = (const int*)  d_in[1];
    const float* eattr    = (const float*)d_in[2];
    const float* emb      = (const float*)d_in[3];
    const float* l1_Wl   = (const float*)d_in[4];
    const float* l1_bl   = (const float*)d_in[5];
    const float* l1_Wr   = (const float*)d_in[6];
    const float* l1_br   = (const float*)d_in[7];
    const float* l1_We   = (const float*)d_in[8];
    const float* l1_att  = (const float*)d_in[9];
    const float* l1_bias = (const float*)d_in[10];
    const float* l2_Wl   = (const float*)d_in[11];
    const float* l2_bl   = (const float*)d_in[12];
    const float* l2_Wr   = (const float*)d_in[13];
    const float* l2_br   = (const float*)d_in[14];
    const float* l2_We   = (const float*)d_in[15];
    const float* l2_att  = (const float*)d_in[16];
    const float* l2_bias = (const float*)d_in[17];
    const float* l3_Wl   = (const float*)d_in[18];
    const float* l3_bl   = (const float*)d_in[19];
    const float* l3_Wr   = (const float*)d_in[20];
    const float* l3_br   = (const float*)d_in[21];
    const float* l3_We   = (const float*)d_in[22];
    const float* l3_att  = (const float*)d_in[23];
    const float* l3_bias = (const float*)d_in[24];
    const float* mlp_W1  = (const float*)d_in[25];
    const float* mlp_b1  = (const float*)d_in[26];
    const float* mlp_W2  = (const float*)d_in[27];
    const float* mlp_b2  = (const float*)d_in[28];
    const float* mlp_W3  = (const float*)d_in[29];
    const float* mlp_b3  = (const float*)d_in[30];

    int n = in_sizes[0];
    int e = in_sizes[1] / 2;
    const int* src = eidx;
    const int* dst = eidx + e;
    float* out = (float*)d_out;

    static bool attr_set = false;
    if (!attr_set) {
        cudaFuncSetAttribute(k_edge_mma, cudaFuncAttributeMaxDynamicSharedMemorySize, SM_EP_TOTAL);
        attr_set = true;
    }

    // ---- prep + layer 1 (edge GEMM stays launch #4 for ncu) ----
    k_prep_w<<<(NCOL * KPAD + 255) / 256, 256>>>(l1_We, l2_We, l3_We);
    k_node1<<<(n + 15) / 16, 256>>>(node_ids, emb, l1_Wl, l1_bl, l1_Wr, l1_br, n);
    k_noop<<<1, 32>>>();
    k_edge_mma<<<(e + 127) / 128, 128, SM_EP_TOTAL>>>(eattr, src, dst, l1_att, e);
    k_node_fin1<<<(n + 15) / 16, 256>>>(l1_bias, l2_Wl, l2_bl, l2_Wr, l2_br, n);

    // ---- layer 2 ----
    k_l2<<<(e + 7) / 8, 256>>>(src, dst, l2_att, e);
    k_node_fin2<<<(n + 15) / 16, 256>>>(l2_bias, l3_Wl, l3_bl, l3_Wr, l3_br, n);

    // ---- layer 3 ----
    k_l3<<<(e + 7) / 8, 128>>>(src, dst, l3_att, e);
    k_node_fin3<<<(n * 16 + 255) / 256, 256>>>(l3_bias, n);

    // ---- edge MLP via P/Q ----
    k_pq<<<(n + 15) / 16, 256>>>(mlp_W1, n);
    k_mlp<<<(e + 63) / 64, 256>>>(src, dst, mlp_b1, mlp_W2, mlp_b2,
                                  mlp_W3, mlp_b3, out, e);
}